// round 5
// baseline (speedup 1.0000x reference)
#include <cuda_runtime.h>
#include <cuda_bf16.h>
#include <math_constants.h>
#include <cstdint>

#define B_    16
#define C_    256
#define HW_   1024
#define NTOK  16384
#define KCODE 8192
#define XQ_SIZE  4194304
#define LOSS_OFF 4194304
#define CODE_OFF 4194305
#define TAU   1e-3f

// A row pitch (bf16): 512 data + 8 pad = 1040 B
#define A_PITCH_B 1040
#define A_BYTES   (128 * A_PITCH_B)          // 133120
// B stage: 256 codes x 64 bf16, row pitch 144 B
#define B_PITCH_B 144
#define B_STAGE_B (256 * B_PITCH_B)          // 36864
#define B_OFF     A_BYTES
#define SMEM_TOTAL (A_BYTES + 2 * B_STAGE_B) // 206848

// ---------------- Device scratch ----------------
__device__ __align__(256) __nv_bfloat16 g_A[NTOK * 512];    // [xh|xl] per token
__device__ __align__(256) __nv_bfloat16 g_Bw[KCODE * 512];  // [eh|el] per code
__device__ __align__(256) float g_hn[KCODE];                // 0.5*||e||^2
__device__ int    g_code[NTOK];
__device__ int    g_flag[NTOK];
__device__ double g_partial[512];

// ---------------- helpers ----------------
__device__ __forceinline__ uint32_t smem_u32(const void* p) {
    uint32_t a;
    asm("{ .reg .u64 t; cvta.to.shared.u64 t, %1; cvt.u32.u64 %0, t; }" : "=r"(a) : "l"(p));
    return a;
}
__device__ __forceinline__ void cp_async16(uint32_t dst, const void* src) {
    asm volatile("cp.async.cg.shared.global [%0], [%1], 16;" :: "r"(dst), "l"(src) : "memory");
}
#define CP_COMMIT() asm volatile("cp.async.commit_group;" ::: "memory")
#define CP_WAIT(n)  asm volatile("cp.async.wait_group %0;" :: "n"(n) : "memory")

__device__ __forceinline__ void ldsm4(uint32_t* r, uint32_t addr) {
    asm volatile("ldmatrix.sync.aligned.m8n8.x4.shared.b16 {%0,%1,%2,%3}, [%4];"
                 : "=r"(r[0]), "=r"(r[1]), "=r"(r[2]), "=r"(r[3]) : "r"(addr));
}
__device__ __forceinline__ void mma_bf16(float* d, const uint32_t* a, const uint32_t* b) {
    asm volatile("mma.sync.aligned.m16n8k16.row.col.f32.bf16.bf16.f32 "
                 "{%0,%1,%2,%3}, {%4,%5,%6,%7}, {%8,%9}, {%0,%1,%2,%3};"
                 : "+f"(d[0]), "+f"(d[1]), "+f"(d[2]), "+f"(d[3])
                 : "r"(a[0]), "r"(a[1]), "r"(a[2]), "r"(a[3]), "r"(b[0]), "r"(b[1]));
}
__device__ __forceinline__ float f4get(const float4& v, int q) {
    switch (q) { case 0: return v.x; case 1: return v.y; case 2: return v.z; default: return v.w; }
}
// running (best, second, idx); ascending code order; strict > keeps first index;
// exact tie v==best hits (v > second) and sets second=best -> gap 0 -> flagged.
__device__ __forceinline__ void upd(float& b, float& s, int& i, float v, int c) {
    if (v > b) { s = b; b = v; i = c; }
    else if (v > s) s = v;
}

// ---------------- Kernel 1: x -> token-major bf16 hi/lo split ----------------
__global__ void vq_prep(const float* __restrict__ x) {
    __shared__ float tile[32][33];
    int c0 = blockIdx.x << 5, hw0 = blockIdx.y << 5, b = blockIdx.z;
    const float* xb = x + (size_t)b * (C_ * HW_);
#pragma unroll
    for (int k = 0; k < 4; ++k)
        tile[threadIdx.y + k * 8][threadIdx.x] =
            xb[(size_t)(c0 + threadIdx.y + k * 8) * HW_ + hw0 + threadIdx.x];
    __syncthreads();
#pragma unroll
    for (int k = 0; k < 4; ++k) {
        int token = b * HW_ + hw0 + threadIdx.y + k * 8;
        int c = c0 + threadIdx.x;
        float v = tile[threadIdx.x][threadIdx.y + k * 8];
        __nv_bfloat16 h = __float2bfloat16(v);
        g_A[(size_t)token * 512 + c] = h;
        g_A[(size_t)token * 512 + 256 + c] = __float2bfloat16(v - __bfloat162float(h));
    }
}

// ---------------- Kernel 2: half code norms ----------------
__global__ void vq_norms(const float* __restrict__ w) {
    int k = blockIdx.x * 256 + threadIdx.x;
    const float4* r = (const float4*)(w + (size_t)k * C_);
    float s = 0.f;
#pragma unroll 8
    for (int i = 0; i < 64; ++i) {
        float4 v = r[i];
        s += v.x * v.x + v.y * v.y + v.z * v.z + v.w * v.w;
    }
    g_hn[k] = 0.5f * s;
}

// ---------------- Kernel 3: weights -> bf16 hi/lo split ----------------
__global__ void vq_split_w(const float* __restrict__ w) {
    int k = blockIdx.x, c = threadIdx.x;
    float e = w[(size_t)k * C_ + c];
    __nv_bfloat16 h = __float2bfloat16(e);
    g_Bw[(size_t)k * 512 + c] = h;
    g_Bw[(size_t)k * 512 + 256 + c] = __float2bfloat16(e - __bfloat162float(h));
}

// ---------------- Kernel 4: HMMA GEMM + fused argmax ----------------
// 3-product split: score = xh.eh + xl.eh + xh.el  (xl.el ~3e-6 dropped).
// B slabs 0-3 of each chunk hold eh (paired with A-hi AND A-lo);
// slabs 4-7 hold el (paired with A-hi only).
__device__ __forceinline__ void issue_slab(uint32_t sb, int slot, int s, int tid) {
    const __nv_bfloat16* src = g_Bw + (size_t)(s >> 3) * (256 * 512) + (s & 7) * 64;
    uint32_t dst = sb + B_OFF + slot * B_STAGE_B;
#pragma unroll
    for (int i = 0; i < 8; ++i) {
        int g = i * 256 + tid;
        int code = g >> 3, q = g & 7;
        cp_async16(dst + code * B_PITCH_B + q * 16, src + (size_t)code * 512 + q * 8);
    }
}

__global__ void __launch_bounds__(256, 1) vq_argmax_mma() {
    extern __shared__ char smem[];
    uint32_t sb = smem_u32(smem);
    int tid = threadIdx.x, lane = tid & 31, wid = tid >> 5;
    int wm = wid >> 2, wn = wid & 3;
    int t0g = blockIdx.x << 7;

    // Prologue: A tile + slab0 (group0), slab1 (group1)
#pragma unroll
    for (int i = 0; i < 32; ++i) {
        int g = i * 256 + tid;
        int row = g >> 6, q = g & 63;
        cp_async16(sb + row * A_PITCH_B + q * 16, g_A + (size_t)(t0g + row) * 512 + q * 8);
    }
    issue_slab(sb, 0, 0, tid);
    CP_COMMIT();
    issue_slab(sb, 1, 1, tid);
    CP_COMMIT();

    // lane-invariant ldmatrix address components
    uint32_t a_base = sb + (wm * 64 + (lane & 15)) * A_PITCH_B + (lane >> 4) * 16;
    uint32_t b_base = B_OFF +
        (uint32_t)(wn * 64 + ((lane >> 4) & 1) * 8 + (lane & 7)) * B_PITCH_B +
        ((lane >> 3) & 1) * 16;

    float tb[8], ts[8]; int tix[8];
#pragma unroll
    for (int k = 0; k < 8; ++k) { tb[k] = -CUDART_INF_F; ts[k] = -CUDART_INF_F; tix[k] = 0x7fffffff; }

    for (int ch = 0; ch < 32; ++ch) {
        float d[4][8][4];
#pragma unroll
        for (int mt = 0; mt < 4; ++mt)
#pragma unroll
            for (int nt = 0; nt < 8; ++nt)
#pragma unroll
                for (int q = 0; q < 4; ++q) d[mt][nt][q] = 0.f;

        for (int sl = 0; sl < 8; ++sl) {
            int s = ch * 8 + sl;
            if (s < 255) { CP_WAIT(1); } else { CP_WAIT(0); }
            __syncthreads();
            uint32_t bst = sb + (s & 1) * B_STAGE_B + b_base;
            // A-hi byte offset for this B slab: eh slabs (0-3) pair with hi
            // chunk sl; el slabs (4-7) pair with hi chunk sl-4. Both = (sl&3).
            uint32_t ahi = (uint32_t)((sl & 3) * 128);
            bool is_eh = (sl < 4);
#pragma unroll
            for (int j = 0; j < 4; ++j) {
                // B fragments (shared by both A passes)
                uint32_t br[8][2];
#pragma unroll
                for (int p = 0; p < 4; ++p) {
                    uint32_t r[4];
                    ldsm4(r, bst + p * (16 * B_PITCH_B) + j * 32);
                    br[2 * p][0] = r[0]; br[2 * p][1] = r[1];
                    br[2 * p + 1][0] = r[2]; br[2 * p + 1][1] = r[3];
                }
                // Pass 1: A-hi x B
                {
                    uint32_t ar[4][4];
#pragma unroll
                    for (int mt = 0; mt < 4; ++mt)
                        ldsm4(ar[mt], a_base + mt * (16 * A_PITCH_B) + ahi + j * 32);
#pragma unroll
                    for (int mt = 0; mt < 4; ++mt)
#pragma unroll
                        for (int nt = 0; nt < 8; ++nt)
                            mma_bf16(d[mt][nt], ar[mt], br[nt]);
                }
                // Pass 2 (eh slabs only): A-lo x B  (lo starts at byte 512)
                if (is_eh) {
                    uint32_t ar[4][4];
#pragma unroll
                    for (int mt = 0; mt < 4; ++mt)
                        ldsm4(ar[mt], a_base + mt * (16 * A_PITCH_B) + 512 + ahi + j * 32);
#pragma unroll
                    for (int mt = 0; mt < 4; ++mt)
#pragma unroll
                        for (int nt = 0; nt < 8; ++nt)
                            mma_bf16(d[mt][nt], ar[mt], br[nt]);
                }
            }
            __syncthreads();
            int s2 = s + 2;
            if (s2 < 256) { issue_slab(sb, s2 & 1, s2, tid); CP_COMMIT(); }
        }

        // chunk epilogue: scores = dot - hn; running argmax in registers
        int n0 = ch * 256 + wn * 64 + (lane & 3) * 2;
#pragma unroll
        for (int mt = 0; mt < 4; ++mt) {
#pragma unroll
            for (int nt = 0; nt < 8; ++nt) {
                int c0 = n0 + nt * 8;
                float2 h = __ldg((const float2*)(g_hn + c0));
                upd(tb[2 * mt], ts[2 * mt], tix[2 * mt], d[mt][nt][0] - h.x, c0);
                upd(tb[2 * mt], ts[2 * mt], tix[2 * mt], d[mt][nt][1] - h.y, c0 + 1);
                upd(tb[2 * mt + 1], ts[2 * mt + 1], tix[2 * mt + 1], d[mt][nt][2] - h.x, c0);
                upd(tb[2 * mt + 1], ts[2 * mt + 1], tix[2 * mt + 1], d[mt][nt][3] - h.y, c0 + 1);
            }
        }
    }

    // merge across the 4 lanes of each quad (different code columns)
#pragma unroll
    for (int k = 0; k < 8; ++k) {
#pragma unroll
        for (int off = 1; off <= 2; off <<= 1) {
            float ob = __shfl_xor_sync(0xffffffffu, tb[k], off);
            float os = __shfl_xor_sync(0xffffffffu, ts[k], off);
            int   oi = __shfl_xor_sync(0xffffffffu, tix[k], off);
            if (ob > tb[k]) { ts[k] = fmaxf(tb[k], os); tb[k] = ob; tix[k] = oi; }
            else if (ob == tb[k]) { ts[k] = tb[k]; if (oi < tix[k]) tix[k] = oi; }
            else { ts[k] = fmaxf(ts[k], ob); }
        }
    }

    __syncthreads();   // done with A/B smem; reuse for reduction
    float* rb = (float*)smem;          // [4][128]
    float* rs = rb + 512;              // [4][128]
    int*   ri = (int*)(rs + 512);      // [4][128]
    if ((lane & 3) == 0) {
#pragma unroll
        for (int k = 0; k < 8; ++k) {
            int tl = wm * 64 + (k >> 1) * 16 + (lane >> 2) + (k & 1) * 8;
            rb[wn * 128 + tl] = tb[k];
            rs[wn * 128 + tl] = ts[k];
            ri[wn * 128 + tl] = tix[k];
        }
    }
    __syncthreads();
    if (tid < 128) {
        float b = rb[tid], s = rs[tid]; int i = ri[tid];
#pragma unroll
        for (int w = 1; w < 4; ++w) {
            float ob = rb[w * 128 + tid], os = rs[w * 128 + tid];
            int oi = ri[w * 128 + tid];
            if (ob > b) { s = fmaxf(b, os); b = ob; i = oi; }
            else if (ob == b) { s = b; if (oi < i) i = oi; }
            else { s = fmaxf(s, ob); }
        }
        g_code[t0g + tid] = i;
        g_flag[t0g + tid] = (b - s < TAU) ? 1 : 0;
    }
}

// ---------------- Kernel 5: exact fp32 rescan for flagged tokens ----------
__global__ void vq_rescore(const float* __restrict__ x, const float* __restrict__ w) {
    int t = blockIdx.x;
    if (g_flag[t] == 0) return;
    __shared__ float xs[256];
    __shared__ float bv[128];
    __shared__ int   bidx[128];
    int b = t >> 10, hw = t & 1023;
    for (int c = threadIdx.x; c < 256; c += 128)
        xs[c] = x[((size_t)b * 256 + c) * 1024 + hw];
    __syncthreads();
    float best = -CUDART_INF_F; int bi = 0x7fffffff;
    const float4* xv4 = (const float4*)xs;
    for (int k = threadIdx.x; k < KCODE; k += 128) {
        const float4* wr = (const float4*)(w + (size_t)k * 256);
        float s0 = 0.f, s1 = 0.f, s2 = 0.f, s3 = 0.f;
#pragma unroll 8
        for (int i = 0; i < 64; ++i) {
            float4 v = wr[i], xv = xv4[i];
            s0 += v.x * xv.x; s1 += v.y * xv.y; s2 += v.z * xv.z; s3 += v.w * xv.w;
        }
        float s = (s0 + s1) + (s2 + s3) - g_hn[k];
        if (s > best) { best = s; bi = k; }
    }
    bv[threadIdx.x] = best; bidx[threadIdx.x] = bi;
    __syncthreads();
    for (int off = 64; off > 0; off >>= 1) {
        if (threadIdx.x < off) {
            float o = bv[threadIdx.x + off]; int oi = bidx[threadIdx.x + off];
            if (o > bv[threadIdx.x] || (o == bv[threadIdx.x] && oi < bidx[threadIdx.x])) {
                bv[threadIdx.x] = o; bidx[threadIdx.x] = oi;
            }
        }
        __syncthreads();
    }
    if (threadIdx.x == 0) g_code[t] = bidx[0];
}

// ---------------- Kernel 6: gather x_q + loss partials ----------------
__global__ void vq_gather(const float* __restrict__ x, const float* __restrict__ w,
                          float* __restrict__ out) {
    int bx = blockIdx.x;
    int b = bx >> 5, hw0 = (bx & 31) << 5;
    int tid = threadIdx.x;
    int hwl = tid & 31, cg = tid >> 5;
    int t = b * HW_ + hw0 + hwl;
    int k = g_code[t];
    const float* e  = w + (size_t)k * C_;
    const float* xb = x + (size_t)b * (C_ * HW_) + hw0 + hwl;
    float* ob = out + (size_t)b * (C_ * HW_) + hw0 + hwl;
    float ls = 0.f;
#pragma unroll
    for (int p = 0; p < 8; ++p) {
        int c0 = ((p << 3) + cg) << 2;
        float4 ev = *(const float4*)(e + c0);
#pragma unroll
        for (int j = 0; j < 4; ++j) {
            int c = c0 + j;
            float v  = f4get(ev, j);
            float xv = xb[(size_t)c * HW_];
            ob[(size_t)c * HW_] = v;
            float dd = v - xv;
            ls += dd * dd;
        }
    }
#pragma unroll
    for (int off = 16; off > 0; off >>= 1)
        ls += __shfl_down_sync(0xffffffffu, ls, off);
    __shared__ float ws[8];
    if ((tid & 31) == 0) ws[tid >> 5] = ls;
    __syncthreads();
    if (tid == 0) {
        float s = 0.f;
#pragma unroll
        for (int i = 0; i < 8; ++i) s += ws[i];
        g_partial[bx] = (double)s;
    }
}

// ---------------- Kernel 7: finalize ----------------
__global__ void vq_finalize(float* __restrict__ out) {
    int idx = blockIdx.x * 256 + threadIdx.x;
    if (idx < NTOK) out[CODE_OFF + idx] = (float)g_code[idx];
    if (idx == 0) {
        double s = 0.0;
        for (int i = 0; i < 512; ++i) s += g_partial[i];
        out[LOSS_OFF] = (float)(1.25 * s / (double)XQ_SIZE);
    }
}

// ---------------- Launch ----------------
extern "C" void kernel_launch(void* const* d_in, const int* in_sizes, int n_in,
                              void* d_out, int out_size) {
    const float* x = (const float*)d_in[0];
    const float* w = (const float*)d_in[1];
    float* out = (float*)d_out;

    cudaFuncSetAttribute((const void*)vq_argmax_mma,
                         cudaFuncAttributeMaxDynamicSharedMemorySize, SMEM_TOTAL);

    vq_prep<<<dim3(8, 32, 16), dim3(32, 8)>>>(x);
    vq_norms<<<32, 256>>>(w);
    vq_split_w<<<KCODE, 256>>>(w);
    vq_argmax_mma<<<128, 256, SMEM_TOTAL>>>();
    vq_rescore<<<NTOK, 128>>>(x, w);
    vq_gather<<<512, 256>>>(x, w, out);
    vq_finalize<<<64, 256>>>(out);
}

// round 6
// speedup vs baseline: 1.2523x; 1.2523x over previous
#include <cuda_runtime.h>
#include <cuda_bf16.h>
#include <math_constants.h>
#include <cstdint>

#define B_    16
#define C_    256
#define HW_   1024
#define NTOK  16384
#define KCODE 8192
#define XQ_SIZE  4194304
#define LOSS_OFF 4194304
#define CODE_OFF 4194305
#define TAU   4e-4f

// A row pitch (bf16): 512 data + 8 pad = 1040 B
#define A_PITCH_B 1040
#define A_BYTES   (128 * A_PITCH_B)          // 133120
// B stage: 256 codes x 64 bf16, row pitch 144 B
#define B_PITCH_B 144
#define B_STAGE_B (256 * B_PITCH_B)          // 36864
#define B_OFF     A_BYTES
#define HN2_OFF   (A_BYTES + 2 * B_STAGE_B)  // 206848 (2 x 1KB hn buffers)
#define SMEM_TOTAL (HN2_OFF + 2048)          // 208896

// ---------------- Device scratch ----------------
__device__ __align__(256) __nv_bfloat16 g_A[NTOK * 512];    // [xh|xl] per token
__device__ __align__(256) __nv_bfloat16 g_Bw[KCODE * 512];  // [eh|el] per code
__device__ __align__(256) float g_hn[KCODE];                // 0.5*||e||^2
__device__ int    g_code[NTOK];
__device__ int    g_qn;
__device__ int    g_queue[NTOK];
__device__ double g_partial[512];

// ---------------- helpers ----------------
__device__ __forceinline__ uint32_t smem_u32(const void* p) {
    uint32_t a;
    asm("{ .reg .u64 t; cvta.to.shared.u64 t, %1; cvt.u32.u64 %0, t; }" : "=r"(a) : "l"(p));
    return a;
}
__device__ __forceinline__ void cp_async16(uint32_t dst, const void* src) {
    asm volatile("cp.async.cg.shared.global [%0], [%1], 16;" :: "r"(dst), "l"(src) : "memory");
}
#define CP_COMMIT() asm volatile("cp.async.commit_group;" ::: "memory")
#define CP_WAIT(n)  asm volatile("cp.async.wait_group %0;" :: "n"(n) : "memory")

__device__ __forceinline__ void ldsm4(uint32_t* r, uint32_t addr) {
    asm volatile("ldmatrix.sync.aligned.m8n8.x4.shared.b16 {%0,%1,%2,%3}, [%4];"
                 : "=r"(r[0]), "=r"(r[1]), "=r"(r[2]), "=r"(r[3]) : "r"(addr));
}
__device__ __forceinline__ void mma_bf16(float* d, const uint32_t* a, const uint32_t* b) {
    asm volatile("mma.sync.aligned.m16n8k16.row.col.f32.bf16.bf16.f32 "
                 "{%0,%1,%2,%3}, {%4,%5,%6,%7}, {%8,%9}, {%0,%1,%2,%3};"
                 : "+f"(d[0]), "+f"(d[1]), "+f"(d[2]), "+f"(d[3])
                 : "r"(a[0]), "r"(a[1]), "r"(a[2]), "r"(a[3]), "r"(b[0]), "r"(b[1]));
}
__device__ __forceinline__ float f4get(const float4& v, int q) {
    switch (q) { case 0: return v.x; case 1: return v.y; case 2: return v.z; default: return v.w; }
}
__device__ __forceinline__ void upd(float& b, float& s, int& i, float v, int c) {
    if (v > b) { s = b; b = v; i = c; }
    else if (v > s) s = v;
}

// ---------------- Kernel 1: x -> token-major bf16 hi/lo split ----------------
__global__ void vq_prep(const float* __restrict__ x) {
    __shared__ float tile[32][33];
    int c0 = blockIdx.x << 5, hw0 = blockIdx.y << 5, b = blockIdx.z;
    const float* xb = x + (size_t)b * (C_ * HW_);
#pragma unroll
    for (int k = 0; k < 4; ++k)
        tile[threadIdx.y + k * 8][threadIdx.x] =
            xb[(size_t)(c0 + threadIdx.y + k * 8) * HW_ + hw0 + threadIdx.x];
    __syncthreads();
#pragma unroll
    for (int k = 0; k < 4; ++k) {
        int token = b * HW_ + hw0 + threadIdx.y + k * 8;
        int c = c0 + threadIdx.x;
        float v = tile[threadIdx.x][threadIdx.y + k * 8];
        __nv_bfloat16 h = __float2bfloat16(v);
        g_A[(size_t)token * 512 + c] = h;
        g_A[(size_t)token * 512 + 256 + c] = __float2bfloat16(v - __bfloat162float(h));
    }
}

// ---------------- Kernel 2: half code norms (+ queue reset) ----------------
__global__ void vq_norms(const float* __restrict__ w) {
    if (blockIdx.x == 0 && threadIdx.x == 0) g_qn = 0;
    int k = blockIdx.x * 256 + threadIdx.x;
    const float4* r = (const float4*)(w + (size_t)k * C_);
    float s = 0.f;
#pragma unroll 8
    for (int i = 0; i < 64; ++i) {
        float4 v = r[i];
        s += v.x * v.x + v.y * v.y + v.z * v.z + v.w * v.w;
    }
    g_hn[k] = 0.5f * s;
}

// ---------------- Kernel 3: weights -> bf16 hi/lo split ----------------
__global__ void vq_split_w(const float* __restrict__ w) {
    int k = blockIdx.x, c = threadIdx.x;
    float e = w[(size_t)k * C_ + c];
    __nv_bfloat16 h = __float2bfloat16(e);
    g_Bw[(size_t)k * 512 + c] = h;
    g_Bw[(size_t)k * 512 + 256 + c] = __float2bfloat16(e - __bfloat162float(h));
}

// ---------------- Kernel 4: HMMA GEMM + fused argmax ----------------
// score = xh.eh + xl.eh + xh.el  (xl.el ~<=1e-4 dropped; TAU=4e-4 flags ties)
__device__ __forceinline__ void issue_slab(uint32_t sb, int slot, int s, int tid) {
    const __nv_bfloat16* src = g_Bw + (size_t)(s >> 3) * (256 * 512) + (s & 7) * 64;
    uint32_t dst = sb + B_OFF + slot * B_STAGE_B;
#pragma unroll
    for (int i = 0; i < 8; ++i) {
        int g = i * 256 + tid;
        int code = g >> 3, q = g & 7;
        cp_async16(dst + code * B_PITCH_B + q * 16, src + (size_t)code * 512 + q * 8);
    }
}

__global__ void __launch_bounds__(256, 1) vq_argmax_mma() {
    extern __shared__ char smem[];
    uint32_t sb = smem_u32(smem);
    int tid = threadIdx.x, lane = tid & 31, wid = tid >> 5;
    int wm = wid >> 2, wn = wid & 3;
    int t0g = blockIdx.x << 7;

    // Prologue: A tile + slab0 + hn(chunk0) in group0; slab1 in group1
#pragma unroll
    for (int i = 0; i < 32; ++i) {
        int g = i * 256 + tid;
        int row = g >> 6, q = g & 63;
        cp_async16(sb + row * A_PITCH_B + q * 16, g_A + (size_t)(t0g + row) * 512 + q * 8);
    }
    issue_slab(sb, 0, 0, tid);
    if (tid < 64) cp_async16(sb + HN2_OFF + tid * 16, g_hn + tid * 4);
    CP_COMMIT();
    issue_slab(sb, 1, 1, tid);
    CP_COMMIT();

    uint32_t a_base = sb + (wm * 64 + (lane & 15)) * A_PITCH_B + (lane >> 4) * 16;
    uint32_t b_base = B_OFF +
        (uint32_t)(wn * 64 + ((lane >> 4) & 1) * 8 + (lane & 7)) * B_PITCH_B +
        ((lane >> 3) & 1) * 16;

    float tb[8], ts[8]; int tix[8];
#pragma unroll
    for (int k = 0; k < 8; ++k) { tb[k] = -CUDART_INF_F; ts[k] = -CUDART_INF_F; tix[k] = 0x7fffffff; }

    for (int ch = 0; ch < 32; ++ch) {
        float d[4][8][4];
#pragma unroll
        for (int mt = 0; mt < 4; ++mt)
#pragma unroll
            for (int nt = 0; nt < 8; ++nt)
#pragma unroll
                for (int q = 0; q < 4; ++q) d[mt][nt][q] = 0.f;

        for (int sl = 0; sl < 8; ++sl) {
            int s = ch * 8 + sl;
            if (s < 255) { CP_WAIT(1); } else { CP_WAIT(0); }
            __syncthreads();
            uint32_t bst = sb + (s & 1) * B_STAGE_B + b_base;
            uint32_t ahi = (uint32_t)((sl & 3) * 128);
            bool is_eh = (sl < 4);
#pragma unroll
            for (int j = 0; j < 4; ++j) {
                // all ldsm issued before the MMA streak
                uint32_t br[8][2];
#pragma unroll
                for (int p = 0; p < 4; ++p) {
                    uint32_t r[4];
                    ldsm4(r, bst + p * (16 * B_PITCH_B) + j * 32);
                    br[2 * p][0] = r[0]; br[2 * p][1] = r[1];
                    br[2 * p + 1][0] = r[2]; br[2 * p + 1][1] = r[3];
                }
                uint32_t arh[4][4];
#pragma unroll
                for (int mt = 0; mt < 4; ++mt)
                    ldsm4(arh[mt], a_base + mt * (16 * A_PITCH_B) + ahi + j * 32);
                uint32_t arl[4][4];
                if (is_eh) {
#pragma unroll
                    for (int mt = 0; mt < 4; ++mt)
                        ldsm4(arl[mt], a_base + mt * (16 * A_PITCH_B) + 512 + ahi + j * 32);
                }
#pragma unroll
                for (int mt = 0; mt < 4; ++mt)
#pragma unroll
                    for (int nt = 0; nt < 8; ++nt)
                        mma_bf16(d[mt][nt], arh[mt], br[nt]);
                if (is_eh) {
#pragma unroll
                    for (int mt = 0; mt < 4; ++mt)
#pragma unroll
                        for (int nt = 0; nt < 8; ++nt)
                            mma_bf16(d[mt][nt], arl[mt], br[nt]);
                }
            }
            __syncthreads();
            int s2 = s + 2;
            if (s2 < 256) {
                issue_slab(sb, s2 & 1, s2, tid);
                if ((s2 & 7) == 0 && tid < 64) {
                    int ch2 = s2 >> 3;
                    cp_async16(sb + HN2_OFF + ((ch2 & 1) << 10) + tid * 16,
                               g_hn + ch2 * 256 + tid * 4);
                }
                CP_COMMIT();
            }
        }

        // chunk epilogue: hn from smem; running argmax in registers
        const float* hnc = (const float*)(smem + HN2_OFF + ((ch & 1) << 10));
        int n0 = ch * 256 + wn * 64 + (lane & 3) * 2;
        int l0 = wn * 64 + (lane & 3) * 2;
#pragma unroll
        for (int mt = 0; mt < 4; ++mt) {
#pragma unroll
            for (int nt = 0; nt < 8; ++nt) {
                int c0 = n0 + nt * 8;
                float2 h = *(const float2*)(hnc + l0 + nt * 8);
                upd(tb[2 * mt], ts[2 * mt], tix[2 * mt], d[mt][nt][0] - h.x, c0);
                upd(tb[2 * mt], ts[2 * mt], tix[2 * mt], d[mt][nt][1] - h.y, c0 + 1);
                upd(tb[2 * mt + 1], ts[2 * mt + 1], tix[2 * mt + 1], d[mt][nt][2] - h.x, c0);
                upd(tb[2 * mt + 1], ts[2 * mt + 1], tix[2 * mt + 1], d[mt][nt][3] - h.y, c0 + 1);
            }
        }
    }

    // merge across the 4 lanes of each quad (different code columns)
#pragma unroll
    for (int k = 0; k < 8; ++k) {
#pragma unroll
        for (int off = 1; off <= 2; off <<= 1) {
            float ob = __shfl_xor_sync(0xffffffffu, tb[k], off);
            float os = __shfl_xor_sync(0xffffffffu, ts[k], off);
            int   oi = __shfl_xor_sync(0xffffffffu, tix[k], off);
            if (ob > tb[k]) { ts[k] = fmaxf(tb[k], os); tb[k] = ob; tix[k] = oi; }
            else if (ob == tb[k]) { ts[k] = tb[k]; if (oi < tix[k]) tix[k] = oi; }
            else { ts[k] = fmaxf(ts[k], ob); }
        }
    }

    __syncthreads();   // done with A/B smem; reuse for reduction
    float* rb = (float*)smem;          // [4][128]
    float* rs = rb + 512;              // [4][128]
    int*   ri = (int*)(rs + 512);      // [4][128]
    if ((lane & 3) == 0) {
#pragma unroll
        for (int k = 0; k < 8; ++k) {
            int tl = wm * 64 + (k >> 1) * 16 + (lane >> 2) + (k & 1) * 8;
            rb[wn * 128 + tl] = tb[k];
            rs[wn * 128 + tl] = ts[k];
            ri[wn * 128 + tl] = tix[k];
        }
    }
    __syncthreads();
    if (tid < 128) {
        float b = rb[tid], s = rs[tid]; int i = ri[tid];
#pragma unroll
        for (int w = 1; w < 4; ++w) {
            float ob = rb[w * 128 + tid], os = rs[w * 128 + tid];
            int oi = ri[w * 128 + tid];
            if (ob > b) { s = fmaxf(b, os); b = ob; i = oi; }
            else if (ob == b) { s = b; if (oi < i) i = oi; }
            else { s = fmaxf(s, ob); }
        }
        g_code[t0g + tid] = i;
        if (b - s < TAU) {
            int p = atomicAdd(&g_qn, 1);
            g_queue[p] = t0g + tid;
        }
    }
}

// ---------------- Kernel 5: exact fp32 rescan over flagged queue ----------
__global__ void vq_rescore(const float* __restrict__ x, const float* __restrict__ w) {
    __shared__ float xs[256];
    __shared__ float bv[128];
    __shared__ int   bidx[128];
    int qn = g_qn;
    for (int qi = blockIdx.x; qi < qn; qi += (int)gridDim.x) {
        int t = g_queue[qi];
        __syncthreads();   // protect xs reuse across queue items
        int b = t >> 10, hw = t & 1023;
        for (int c = threadIdx.x; c < 256; c += 128)
            xs[c] = x[((size_t)b * 256 + c) * 1024 + hw];
        __syncthreads();
        float best = -CUDART_INF_F; int bi = 0x7fffffff;
        const float4* xv4 = (const float4*)xs;
        for (int k = threadIdx.x; k < KCODE; k += 128) {
            const float4* wr = (const float4*)(w + (size_t)k * 256);
            float s0 = 0.f, s1 = 0.f, s2 = 0.f, s3 = 0.f;
#pragma unroll 8
            for (int i = 0; i < 64; ++i) {
                float4 v = wr[i], xv = xv4[i];
                s0 += v.x * xv.x; s1 += v.y * xv.y; s2 += v.z * xv.z; s3 += v.w * xv.w;
            }
            float s = (s0 + s1) + (s2 + s3) - g_hn[k];
            if (s > best) { best = s; bi = k; }
        }
        bv[threadIdx.x] = best; bidx[threadIdx.x] = bi;
        __syncthreads();
        for (int off = 64; off > 0; off >>= 1) {
            if (threadIdx.x < off) {
                float o = bv[threadIdx.x + off]; int oi = bidx[threadIdx.x + off];
                if (o > bv[threadIdx.x] || (o == bv[threadIdx.x] && oi < bidx[threadIdx.x])) {
                    bv[threadIdx.x] = o; bidx[threadIdx.x] = oi;
                }
            }
            __syncthreads();
        }
        if (threadIdx.x == 0) g_code[t] = bidx[0];
    }
}

// ---------------- Kernel 6: gather x_q + loss partials ----------------
__global__ void vq_gather(const float* __restrict__ x, const float* __restrict__ w,
                          float* __restrict__ out) {
    int bx = blockIdx.x;
    int b = bx >> 5, hw0 = (bx & 31) << 5;
    int tid = threadIdx.x;
    int hwl = tid & 31, cg = tid >> 5;
    int t = b * HW_ + hw0 + hwl;
    int k = g_code[t];
    const float* e  = w + (size_t)k * C_;
    const float* xb = x + (size_t)b * (C_ * HW_) + hw0 + hwl;
    float* ob = out + (size_t)b * (C_ * HW_) + hw0 + hwl;
    float ls = 0.f;
#pragma unroll
    for (int p = 0; p < 8; ++p) {
        int c0 = ((p << 3) + cg) << 2;
        float4 ev = *(const float4*)(e + c0);
#pragma unroll
        for (int j = 0; j < 4; ++j) {
            int c = c0 + j;
            float v  = f4get(ev, j);
            float xv = xb[(size_t)c * HW_];
            ob[(size_t)c * HW_] = v;
            float dd = v - xv;
            ls += dd * dd;
        }
    }
#pragma unroll
    for (int off = 16; off > 0; off >>= 1)
        ls += __shfl_down_sync(0xffffffffu, ls, off);
    __shared__ float ws[8];
    if ((tid & 31) == 0) ws[tid >> 5] = ls;
    __syncthreads();
    if (tid == 0) {
        float s = 0.f;
#pragma unroll
        for (int i = 0; i < 8; ++i) s += ws[i];
        g_partial[bx] = (double)s;
    }
}

// ---------------- Kernel 7: finalize ----------------
__global__ void vq_finalize(float* __restrict__ out) {
    int idx = blockIdx.x * 256 + threadIdx.x;
    if (idx < NTOK) out[CODE_OFF + idx] = (float)g_code[idx];
    if (idx == 0) {
        double s = 0.0;
        for (int i = 0; i < 512; ++i) s += g_partial[i];
        out[LOSS_OFF] = (float)(1.25 * s / (double)XQ_SIZE);
    }
}

// ---------------- Launch ----------------
extern "C" void kernel_launch(void* const* d_in, const int* in_sizes, int n_in,
                              void* d_out, int out_size) {
    const float* x = (const float*)d_in[0];
    const float* w = (const float*)d_in[1];
    float* out = (float*)d_out;

    cudaFuncSetAttribute((const void*)vq_argmax_mma,
                         cudaFuncAttributeMaxDynamicSharedMemorySize, SMEM_TOTAL);

    vq_prep<<<dim3(8, 32, 16), dim3(32, 8)>>>(x);
    vq_norms<<<32, 256>>>(w);
    vq_split_w<<<KCODE, 256>>>(w);
    vq_argmax_mma<<<128, 256, SMEM_TOTAL>>>();
    vq_rescore<<<128, 128>>>(x, w);
    vq_gather<<<512, 256>>>(x, w, out);
    vq_finalize<<<64, 256>>>(out);
}

// round 7
// speedup vs baseline: 1.4406x; 1.1504x over previous
#include <cuda_runtime.h>
#include <cuda_fp16.h>
#include <math_constants.h>
#include <cstdint>

#define B_    16
#define C_    256
#define HW_   1024
#define NTOK  16384
#define KCODE 8192
#define XQ_SIZE  4194304
#define LOSS_OFF 4194304
#define CODE_OFF 4194305
#define TAU   1.5e-3f

// A: 128 rows x 512B (256 fp16) + 16 pad = 528B pitch
#define A_PITCH   528
#define A_BYTES   (128 * A_PITCH)            // 67584
// B stage: 256 codes x 256B (eh64|el64 per k-chunk) + 16 pad = 272B pitch
#define B_PITCH   272
#define B_STAGE   (256 * B_PITCH)            // 69632
#define B_OFF     A_BYTES
#define HN_OFF    (A_BYTES + 2 * B_STAGE)    // 206848
#define SMEM_TOTAL (HN_OFF + 2048)           // 208896

// ---------------- Device scratch ----------------
__device__ __align__(256) __half g_A[NTOK * 256];    // xh per token
// per code: 512 fp16 = 4 k-chunks x [eh(64) | el(64)]
__device__ __align__(256) __half g_Bw[KCODE * 512];
__device__ __align__(256) float g_hn[KCODE];
__device__ int    g_code[NTOK];
__device__ int    g_qn;
__device__ int    g_queue[NTOK];
__device__ double g_partial[512];

// ---------------- helpers ----------------
__device__ __forceinline__ uint32_t smem_u32(const void* p) {
    uint32_t a;
    asm("{ .reg .u64 t; cvta.to.shared.u64 t, %1; cvt.u32.u64 %0, t; }" : "=r"(a) : "l"(p));
    return a;
}
__device__ __forceinline__ void cp_async16(uint32_t dst, const void* src) {
    asm volatile("cp.async.cg.shared.global [%0], [%1], 16;" :: "r"(dst), "l"(src) : "memory");
}
#define CP_COMMIT() asm volatile("cp.async.commit_group;" ::: "memory")
#define CP_WAIT(n)  asm volatile("cp.async.wait_group %0;" :: "n"(n) : "memory")

__device__ __forceinline__ void ldsm4(uint32_t* r, uint32_t addr) {
    asm volatile("ldmatrix.sync.aligned.m8n8.x4.shared.b16 {%0,%1,%2,%3}, [%4];"
                 : "=r"(r[0]), "=r"(r[1]), "=r"(r[2]), "=r"(r[3]) : "r"(addr));
}
__device__ __forceinline__ void mma_fp16(float* d, const uint32_t* a, const uint32_t* b) {
    asm volatile("mma.sync.aligned.m16n8k16.row.col.f32.f16.f16.f32 "
                 "{%0,%1,%2,%3}, {%4,%5,%6,%7}, {%8,%9}, {%0,%1,%2,%3};"
                 : "+f"(d[0]), "+f"(d[1]), "+f"(d[2]), "+f"(d[3])
                 : "r"(a[0]), "r"(a[1]), "r"(a[2]), "r"(a[3]), "r"(b[0]), "r"(b[1]));
}
__device__ __forceinline__ float f4get(const float4& v, int q) {
    switch (q) { case 0: return v.x; case 1: return v.y; case 2: return v.z; default: return v.w; }
}
__device__ __forceinline__ void upd(float& b, float& s, int& i, float v, int c) {
    if (v > b) { s = b; b = v; i = c; }
    else if (v > s) s = v;
}

// ---------------- Kernel 1: x -> token-major fp16 ----------------
__global__ void vq_prep(const float* __restrict__ x) {
    __shared__ float tile[32][33];
    int c0 = blockIdx.x << 5, hw0 = blockIdx.y << 5, b = blockIdx.z;
    const float* xb = x + (size_t)b * (C_ * HW_);
#pragma unroll
    for (int k = 0; k < 4; ++k)
        tile[threadIdx.y + k * 8][threadIdx.x] =
            xb[(size_t)(c0 + threadIdx.y + k * 8) * HW_ + hw0 + threadIdx.x];
    __syncthreads();
#pragma unroll
    for (int k = 0; k < 4; ++k) {
        int token = b * HW_ + hw0 + threadIdx.y + k * 8;
        int c = c0 + threadIdx.x;
        g_A[(size_t)token * 256 + c] = __float2half_rn(tile[threadIdx.x][threadIdx.y + k * 8]);
    }
}

// ---------------- Kernel 2: w -> fp16 [eh|el] + hn + queue reset ----------
__global__ void vq_wprep(const float* __restrict__ w) {
    int k = blockIdx.x, c = threadIdx.x;
    if (k == 0 && c == 0) g_qn = 0;
    float e = w[(size_t)k * C_ + c];
    __half h = __float2half_rn(e);
    float el = e - __half2float(h);
    int j = c >> 6, cc = c & 63;
    g_Bw[(size_t)k * 512 + j * 128 + cc] = h;
    g_Bw[(size_t)k * 512 + j * 128 + 64 + cc] = __float2half_rn(el);
    float s = e * e;
#pragma unroll
    for (int off = 16; off > 0; off >>= 1)
        s += __shfl_down_sync(0xffffffffu, s, off);
    __shared__ float ws[8];
    if ((c & 31) == 0) ws[c >> 5] = s;
    __syncthreads();
    if (c == 0) {
        float t = 0.f;
#pragma unroll
        for (int i = 0; i < 8; ++i) t += ws[i];
        g_hn[k] = 0.5f * t;
    }
}

// ---------------- Kernel 3: fp16 HMMA GEMM + fused argmax ----------------
// score = xh.(eh+el); dropped xl.e ~1.4e-4 RMS; TAU=1.5e-3 flags -> exact rescan.
// 128 gstages: gstage gs = chunk (gs>>2) of 256 codes, k-chunk (gs&3) of 64 k.
// Stage row: 256 codes x [eh(64 fp16) | el(64 fp16)].
__device__ __forceinline__ void issue_stage(uint32_t sb, int slot, int gs, int tid) {
    int ch = gs >> 2, st = gs & 3;
    const __half* src = g_Bw + (size_t)ch * (256 * 512) + st * 128;
    uint32_t dst = sb + B_OFF + slot * B_STAGE;
#pragma unroll
    for (int i = 0; i < 16; ++i) {
        int g = i * 256 + tid;
        int code = g >> 4, q = g & 15;
        cp_async16(dst + code * B_PITCH + q * 16, src + (size_t)code * 512 + q * 8);
    }
}

__global__ void __launch_bounds__(256, 1) vq_argmax_mma() {
    extern __shared__ char smem[];
    uint32_t sb = smem_u32(smem);
    int tid = threadIdx.x, lane = tid & 31, wid = tid >> 5;
    int wm = wid >> 2, wn = wid & 3;
    int t0g = blockIdx.x << 7;

    // Prologue: A tile + stage0 + hn(chunk0) in group0; stage1 in group1
#pragma unroll
    for (int i = 0; i < 16; ++i) {
        int g = i * 256 + tid;
        int row = g >> 5, q = g & 31;
        cp_async16(sb + row * A_PITCH + q * 16, g_A + (size_t)(t0g + row) * 256 + q * 8);
    }
    issue_stage(sb, 0, 0, tid);
    if (tid < 64) cp_async16(sb + HN_OFF + tid * 16, g_hn + tid * 4);
    CP_COMMIT();
    issue_stage(sb, 1, 1, tid);
    CP_COMMIT();

    uint32_t a_base = sb + (wm * 64 + (lane & 15)) * A_PITCH + (lane >> 4) * 16;
    uint32_t b_base = B_OFF +
        (uint32_t)(wn * 64 + ((lane >> 4) & 1) * 8 + (lane & 7)) * B_PITCH +
        ((lane >> 3) & 1) * 16;

    float tb[8], ts[8]; int tix[8];
#pragma unroll
    for (int k = 0; k < 8; ++k) { tb[k] = -CUDART_INF_F; ts[k] = -CUDART_INF_F; tix[k] = 0x7fffffff; }

    float d[4][8][4];

    for (int gs = 0; gs < 128; ++gs) {
        int ch = gs >> 2, st = gs & 3;
        if (st == 0) {
#pragma unroll
            for (int mt = 0; mt < 4; ++mt)
#pragma unroll
                for (int nt = 0; nt < 8; ++nt)
#pragma unroll
                    for (int q = 0; q < 4; ++q) d[mt][nt][q] = 0.f;
        }

        CP_WAIT(1);
        __syncthreads();
        uint32_t bst = sb + (gs & 1) * B_STAGE + b_base;
        uint32_t ak = a_base + (uint32_t)(st * 128);
#pragma unroll
        for (int j = 0; j < 4; ++j) {
            // A fragments (shared by eh and el MMAs)
            uint32_t ar[4][4];
#pragma unroll
            for (int mt = 0; mt < 4; ++mt)
                ldsm4(ar[mt], ak + mt * (16 * A_PITCH) + j * 32);
            // eh fragments + MMA
            uint32_t br[8][2];
#pragma unroll
            for (int p = 0; p < 4; ++p) {
                uint32_t r[4];
                ldsm4(r, bst + p * (16 * B_PITCH) + j * 32);
                br[2 * p][0] = r[0]; br[2 * p][1] = r[1];
                br[2 * p + 1][0] = r[2]; br[2 * p + 1][1] = r[3];
            }
#pragma unroll
            for (int mt = 0; mt < 4; ++mt)
#pragma unroll
                for (int nt = 0; nt < 8; ++nt)
                    mma_fp16(d[mt][nt], ar[mt], br[nt]);
            // el fragments + MMA (row bytes 128..255)
#pragma unroll
            for (int p = 0; p < 4; ++p) {
                uint32_t r[4];
                ldsm4(r, bst + p * (16 * B_PITCH) + 128 + j * 32);
                br[2 * p][0] = r[0]; br[2 * p][1] = r[1];
                br[2 * p + 1][0] = r[2]; br[2 * p + 1][1] = r[3];
            }
#pragma unroll
            for (int mt = 0; mt < 4; ++mt)
#pragma unroll
                for (int nt = 0; nt < 8; ++nt)
                    mma_fp16(d[mt][nt], ar[mt], br[nt]);
        }
        __syncthreads();

        int g2 = gs + 2;
        if (g2 < 128) {
            issue_stage(sb, g2 & 1, g2, tid);
            if (st == 0 && tid < 64) {
                int ch2 = ch + 1;   // gs<=124 here, ch2<=31
                cp_async16(sb + HN_OFF + ((ch2 & 1) << 10) + tid * 16,
                           g_hn + ch2 * 256 + tid * 4);
            }
            CP_COMMIT();
        }

        if (st == 3) {
            const float* hnc = (const float*)(smem + HN_OFF + ((ch & 1) << 10));
            int n0 = ch * 256 + wn * 64 + (lane & 3) * 2;
            int l0 = wn * 64 + (lane & 3) * 2;
#pragma unroll
            for (int mt = 0; mt < 4; ++mt) {
#pragma unroll
                for (int nt = 0; nt < 8; ++nt) {
                    int c0 = n0 + nt * 8;
                    float2 h = *(const float2*)(hnc + l0 + nt * 8);
                    upd(tb[2 * mt], ts[2 * mt], tix[2 * mt], d[mt][nt][0] - h.x, c0);
                    upd(tb[2 * mt], ts[2 * mt], tix[2 * mt], d[mt][nt][1] - h.y, c0 + 1);
                    upd(tb[2 * mt + 1], ts[2 * mt + 1], tix[2 * mt + 1], d[mt][nt][2] - h.x, c0);
                    upd(tb[2 * mt + 1], ts[2 * mt + 1], tix[2 * mt + 1], d[mt][nt][3] - h.y, c0 + 1);
                }
            }
        }
    }

    // merge across the 4 lanes of each quad (different code columns)
#pragma unroll
    for (int k = 0; k < 8; ++k) {
#pragma unroll
        for (int off = 1; off <= 2; off <<= 1) {
            float ob = __shfl_xor_sync(0xffffffffu, tb[k], off);
            float os = __shfl_xor_sync(0xffffffffu, ts[k], off);
            int   oi = __shfl_xor_sync(0xffffffffu, tix[k], off);
            if (ob > tb[k]) { ts[k] = fmaxf(tb[k], os); tb[k] = ob; tix[k] = oi; }
            else if (ob == tb[k]) { ts[k] = tb[k]; if (oi < tix[k]) tix[k] = oi; }
            else { ts[k] = fmaxf(ts[k], ob); }
        }
    }

    __syncthreads();   // done with A/B smem; reuse for reduction
    float* rb = (float*)smem;          // [4][128]
    float* rs = rb + 512;              // [4][128]
    int*   ri = (int*)(rs + 512);      // [4][128]
    if ((lane & 3) == 0) {
#pragma unroll
        for (int k = 0; k < 8; ++k) {
            int tl = wm * 64 + (k >> 1) * 16 + (lane >> 2) + (k & 1) * 8;
            rb[wn * 128 + tl] = tb[k];
            rs[wn * 128 + tl] = ts[k];
            ri[wn * 128 + tl] = tix[k];
        }
    }
    __syncthreads();
    if (tid < 128) {
        float b = rb[tid], s = rs[tid]; int i = ri[tid];
#pragma unroll
        for (int w = 1; w < 4; ++w) {
            float ob = rb[w * 128 + tid], os = rs[w * 128 + tid];
            int oi = ri[w * 128 + tid];
            if (ob > b) { s = fmaxf(b, os); b = ob; i = oi; }
            else if (ob == b) { s = b; if (oi < i) i = oi; }
            else { s = fmaxf(s, ob); }
        }
        g_code[t0g + tid] = i;
        if (b - s < TAU) {
            int p = atomicAdd(&g_qn, 1);
            g_queue[p] = t0g + tid;
        }
    }
}

// ---------------- Kernel 4: exact fp32 rescan over flagged queue ----------
__global__ void vq_rescore(const float* __restrict__ x, const float* __restrict__ w) {
    __shared__ float xs[256];
    __shared__ float bv[128];
    __shared__ int   bidx[128];
    int qn = g_qn;
    for (int qi = blockIdx.x; qi < qn; qi += (int)gridDim.x) {
        int t = g_queue[qi];
        __syncthreads();
        int b = t >> 10, hw = t & 1023;
        for (int c = threadIdx.x; c < 256; c += 128)
            xs[c] = x[((size_t)b * 256 + c) * 1024 + hw];
        __syncthreads();
        float best = -CUDART_INF_F; int bi = 0x7fffffff;
        const float4* xv4 = (const float4*)xs;
        for (int k = threadIdx.x; k < KCODE; k += 128) {
            const float4* wr = (const float4*)(w + (size_t)k * 256);
            float s0 = 0.f, s1 = 0.f, s2 = 0.f, s3 = 0.f;
#pragma unroll 8
            for (int i = 0; i < 64; ++i) {
                float4 v = wr[i], xv = xv4[i];
                s0 += v.x * xv.x; s1 += v.y * xv.y; s2 += v.z * xv.z; s3 += v.w * xv.w;
            }
            float s = (s0 + s1) + (s2 + s3) - g_hn[k];
            if (s > best) { best = s; bi = k; }
        }
        bv[threadIdx.x] = best; bidx[threadIdx.x] = bi;
        __syncthreads();
        for (int off = 64; off > 0; off >>= 1) {
            if (threadIdx.x < off) {
                float o = bv[threadIdx.x + off]; int oi = bidx[threadIdx.x + off];
                if (o > bv[threadIdx.x] || (o == bv[threadIdx.x] && oi < bidx[threadIdx.x])) {
                    bv[threadIdx.x] = o; bidx[threadIdx.x] = oi;
                }
            }
            __syncthreads();
        }
        if (threadIdx.x == 0) g_code[t] = bidx[0];
    }
}

// ---------------- Kernel 5: gather x_q + loss partials ----------------
__global__ void vq_gather(const float* __restrict__ x, const float* __restrict__ w,
                          float* __restrict__ out) {
    int bx = blockIdx.x;
    int b = bx >> 5, hw0 = (bx & 31) << 5;
    int tid = threadIdx.x;
    int hwl = tid & 31, cg = tid >> 5;
    int t = b * HW_ + hw0 + hwl;
    int k = g_code[t];
    const float* e  = w + (size_t)k * C_;
    const float* xb = x + (size_t)b * (C_ * HW_) + hw0 + hwl;
    float* ob = out + (size_t)b * (C_ * HW_) + hw0 + hwl;
    float ls = 0.f;
#pragma unroll
    for (int p = 0; p < 8; ++p) {
        int c0 = ((p << 3) + cg) << 2;
        float4 ev = *(const float4*)(e + c0);
#pragma unroll
        for (int j = 0; j < 4; ++j) {
            int c = c0 + j;
            float v  = f4get(ev, j);
            float xv = xb[(size_t)c * HW_];
            ob[(size_t)c * HW_] = v;
            float dd = v - xv;
            ls += dd * dd;
        }
    }
#pragma unroll
    for (int off = 16; off > 0; off >>= 1)
        ls += __shfl_down_sync(0xffffffffu, ls, off);
    __shared__ float ws[8];
    if ((tid & 31) == 0) ws[tid >> 5] = ls;
    __syncthreads();
    if (tid == 0) {
        float s = 0.f;
#pragma unroll
        for (int i = 0; i < 8; ++i) s += ws[i];
        g_partial[bx] = (double)s;
    }
}

// ---------------- Kernel 6: finalize ----------------
__global__ void vq_finalize(float* __restrict__ out) {
    int idx = blockIdx.x * 256 + threadIdx.x;
    if (idx < NTOK) out[CODE_OFF + idx] = (float)g_code[idx];
    if (idx == 0) {
        double s = 0.0;
        for (int i = 0; i < 512; ++i) s += g_partial[i];
        out[LOSS_OFF] = (float)(1.25 * s / (double)XQ_SIZE);
    }
}

// ---------------- Launch ----------------
extern "C" void kernel_launch(void* const* d_in, const int* in_sizes, int n_in,
                              void* d_out, int out_size) {
    const float* x = (const float*)d_in[0];
    const float* w = (const float*)d_in[1];
    float* out = (float*)d_out;

    cudaFuncSetAttribute((const void*)vq_argmax_mma,
                         cudaFuncAttributeMaxDynamicSharedMemorySize, SMEM_TOTAL);

    vq_prep<<<dim3(8, 32, 16), dim3(32, 8)>>>(x);
    vq_wprep<<<KCODE, 256>>>(w);
    vq_argmax_mma<<<128, 256, SMEM_TOTAL>>>();
    vq_rescore<<<128, 128>>>(x, w);
    vq_gather<<<512, 256>>>(x, w, out);
    vq_finalize<<<64, 256>>>(out);
}

// round 8
// speedup vs baseline: 2.5677x; 1.7823x over previous
#include <cuda_runtime.h>
#include <cuda_fp16.h>
#include <math_constants.h>
#include <cstdint>

#define B_    16
#define C_    256
#define HW_   1024
#define NTOK  16384
#define KCODE 8192
#define XQ_SIZE  4194304
#define LOSS_OFF 4194304
#define CODE_OFF 4194305
#define TAU   1.5e-3f

// A: 128 rows x 512B (256 fp16) + 16 pad = 528B pitch
#define A_PITCH   528
#define A_BYTES   (128 * A_PITCH)            // 67584
// B stage: 256 codes x 256B (eh64|el64 per k-chunk) + 16 pad = 272B pitch
#define B_PITCH   272
#define B_STAGE   (256 * B_PITCH)            // 69632
#define B_OFF     A_BYTES
#define HN_OFF    (A_BYTES + 2 * B_STAGE)    // 206848
#define SMEM_TOTAL (HN_OFF + 2048)           // 208896

// rescore smem: cs[64][260] + xsT[256][33]  (floats)
#define RS_CS_F   (64 * 260)
#define RS_XS_F   (256 * 33)
#define RS_SMEM   ((RS_CS_F + RS_XS_F) * 4)  // 100352

// ---------------- Device scratch ----------------
__device__ __align__(256) __half g_A[NTOK * 256];    // xh per token
__device__ __align__(256) __half g_Bw[KCODE * 512];  // per code: 4 x [eh(64)|el(64)]
__device__ __align__(256) float g_hn[KCODE];
__device__ int    g_code[NTOK];
__device__ int    g_flag[NTOK];
__device__ int    g_qn;
__device__ int    g_queue[NTOK];
__device__ unsigned long long g_best64[NTOK];
__device__ double g_partial[512];

// ---------------- helpers ----------------
__device__ __forceinline__ uint32_t smem_u32(const void* p) {
    uint32_t a;
    asm("{ .reg .u64 t; cvta.to.shared.u64 t, %1; cvt.u32.u64 %0, t; }" : "=r"(a) : "l"(p));
    return a;
}
__device__ __forceinline__ void cp_async16(uint32_t dst, const void* src) {
    asm volatile("cp.async.cg.shared.global [%0], [%1], 16;" :: "r"(dst), "l"(src) : "memory");
}
#define CP_COMMIT() asm volatile("cp.async.commit_group;" ::: "memory")
#define CP_WAIT(n)  asm volatile("cp.async.wait_group %0;" :: "n"(n) : "memory")

__device__ __forceinline__ void ldsm4(uint32_t* r, uint32_t addr) {
    asm volatile("ldmatrix.sync.aligned.m8n8.x4.shared.b16 {%0,%1,%2,%3}, [%4];"
                 : "=r"(r[0]), "=r"(r[1]), "=r"(r[2]), "=r"(r[3]) : "r"(addr));
}
__device__ __forceinline__ void mma_fp16(float* d, const uint32_t* a, const uint32_t* b) {
    asm volatile("mma.sync.aligned.m16n8k16.row.col.f32.f16.f16.f32 "
                 "{%0,%1,%2,%3}, {%4,%5,%6,%7}, {%8,%9}, {%0,%1,%2,%3};"
                 : "+f"(d[0]), "+f"(d[1]), "+f"(d[2]), "+f"(d[3])
                 : "r"(a[0]), "r"(a[1]), "r"(a[2]), "r"(a[3]), "r"(b[0]), "r"(b[1]));
}
__device__ __forceinline__ float f4get(const float4& v, int q) {
    switch (q) { case 0: return v.x; case 1: return v.y; case 2: return v.z; default: return v.w; }
}
__device__ __forceinline__ void upd(float& b, float& s, int& i, float v, int c) {
    if (v > b) { s = b; b = v; i = c; }
    else if (v > s) s = v;
}
// order-preserving (score, idx) pack: higher score wins; ties -> smaller idx.
__device__ __forceinline__ unsigned long long pack_si(float s, int idx) {
    uint32_t u = __float_as_uint(s);
    u = (u & 0x80000000u) ? ~u : (u | 0x80000000u);
    return ((unsigned long long)u << 32) | (uint32_t)(0xFFFFFFFFu - (uint32_t)idx);
}

// ---------------- Kernel 1: x -> token-major fp16 ----------------
__global__ void vq_prep(const float* __restrict__ x) {
    __shared__ float tile[32][33];
    int c0 = blockIdx.x << 5, hw0 = blockIdx.y << 5, b = blockIdx.z;
    const float* xb = x + (size_t)b * (C_ * HW_);
#pragma unroll
    for (int k = 0; k < 4; ++k)
        tile[threadIdx.y + k * 8][threadIdx.x] =
            xb[(size_t)(c0 + threadIdx.y + k * 8) * HW_ + hw0 + threadIdx.x];
    __syncthreads();
#pragma unroll
    for (int k = 0; k < 4; ++k) {
        int token = b * HW_ + hw0 + threadIdx.y + k * 8;
        int c = c0 + threadIdx.x;
        g_A[(size_t)token * 256 + c] = __float2half_rn(tile[threadIdx.x][threadIdx.y + k * 8]);
    }
}

// ---------------- Kernel 2: w -> fp16 [eh|el] + hn + queue reset ----------
__global__ void vq_wprep(const float* __restrict__ w) {
    int k = blockIdx.x, c = threadIdx.x;
    if (k == 0 && c == 0) g_qn = 0;
    float e = w[(size_t)k * C_ + c];
    __half h = __float2half_rn(e);
    float el = e - __half2float(h);
    int j = c >> 6, cc = c & 63;
    g_Bw[(size_t)k * 512 + j * 128 + cc] = h;
    g_Bw[(size_t)k * 512 + j * 128 + 64 + cc] = __float2half_rn(el);
    float s = e * e;
#pragma unroll
    for (int off = 16; off > 0; off >>= 1)
        s += __shfl_down_sync(0xffffffffu, s, off);
    __shared__ float ws[8];
    if ((c & 31) == 0) ws[c >> 5] = s;
    __syncthreads();
    if (c == 0) {
        float t = 0.f;
#pragma unroll
        for (int i = 0; i < 8; ++i) t += ws[i];
        g_hn[k] = 0.5f * t;
    }
}

// ---------------- Kernel 3: fp16 HMMA GEMM + fused argmax ----------------
__device__ __forceinline__ void issue_stage(uint32_t sb, int slot, int gs, int tid) {
    int ch = gs >> 2, st = gs & 3;
    const __half* src = g_Bw + (size_t)ch * (256 * 512) + st * 128;
    uint32_t dst = sb + B_OFF + slot * B_STAGE;
#pragma unroll
    for (int i = 0; i < 16; ++i) {
        int g = i * 256 + tid;
        int code = g >> 4, q = g & 15;
        cp_async16(dst + code * B_PITCH + q * 16, src + (size_t)code * 512 + q * 8);
    }
}

__global__ void __launch_bounds__(256, 1) vq_argmax_mma() {
    extern __shared__ char smem[];
    uint32_t sb = smem_u32(smem);
    int tid = threadIdx.x, lane = tid & 31, wid = tid >> 5;
    int wm = wid >> 2, wn = wid & 3;
    int t0g = blockIdx.x << 7;

#pragma unroll
    for (int i = 0; i < 16; ++i) {
        int g = i * 256 + tid;
        int row = g >> 5, q = g & 31;
        cp_async16(sb + row * A_PITCH + q * 16, g_A + (size_t)(t0g + row) * 256 + q * 8);
    }
    issue_stage(sb, 0, 0, tid);
    if (tid < 64) cp_async16(sb + HN_OFF + tid * 16, g_hn + tid * 4);
    CP_COMMIT();
    issue_stage(sb, 1, 1, tid);
    CP_COMMIT();

    uint32_t a_base = sb + (wm * 64 + (lane & 15)) * A_PITCH + (lane >> 4) * 16;
    uint32_t b_base = B_OFF +
        (uint32_t)(wn * 64 + ((lane >> 4) & 1) * 8 + (lane & 7)) * B_PITCH +
        ((lane >> 3) & 1) * 16;

    float tb[8], ts[8]; int tix[8];
#pragma unroll
    for (int k = 0; k < 8; ++k) { tb[k] = -CUDART_INF_F; ts[k] = -CUDART_INF_F; tix[k] = 0x7fffffff; }

    float d[4][8][4];

    for (int gs = 0; gs < 128; ++gs) {
        int ch = gs >> 2, st = gs & 3;
        if (st == 0) {
#pragma unroll
            for (int mt = 0; mt < 4; ++mt)
#pragma unroll
                for (int nt = 0; nt < 8; ++nt)
#pragma unroll
                    for (int q = 0; q < 4; ++q) d[mt][nt][q] = 0.f;
        }

        CP_WAIT(1);
        __syncthreads();
        uint32_t bst = sb + (gs & 1) * B_STAGE + b_base;
        uint32_t ak = a_base + (uint32_t)(st * 128);
#pragma unroll
        for (int j = 0; j < 4; ++j) {
            uint32_t ar[4][4];
#pragma unroll
            for (int mt = 0; mt < 4; ++mt)
                ldsm4(ar[mt], ak + mt * (16 * A_PITCH) + j * 32);
            uint32_t br[8][2];
#pragma unroll
            for (int p = 0; p < 4; ++p) {
                uint32_t r[4];
                ldsm4(r, bst + p * (16 * B_PITCH) + j * 32);
                br[2 * p][0] = r[0]; br[2 * p][1] = r[1];
                br[2 * p + 1][0] = r[2]; br[2 * p + 1][1] = r[3];
            }
#pragma unroll
            for (int mt = 0; mt < 4; ++mt)
#pragma unroll
                for (int nt = 0; nt < 8; ++nt)
                    mma_fp16(d[mt][nt], ar[mt], br[nt]);
#pragma unroll
            for (int p = 0; p < 4; ++p) {
                uint32_t r[4];
                ldsm4(r, bst + p * (16 * B_PITCH) + 128 + j * 32);
                br[2 * p][0] = r[0]; br[2 * p][1] = r[1];
                br[2 * p + 1][0] = r[2]; br[2 * p + 1][1] = r[3];
            }
#pragma unroll
            for (int mt = 0; mt < 4; ++mt)
#pragma unroll
                for (int nt = 0; nt < 8; ++nt)
                    mma_fp16(d[mt][nt], ar[mt], br[nt]);
        }
        __syncthreads();

        int g2 = gs + 2;
        if (g2 < 128) {
            issue_stage(sb, g2 & 1, g2, tid);
            if (st == 0 && tid < 64) {
                int ch2 = ch + 1;
                cp_async16(sb + HN_OFF + ((ch2 & 1) << 10) + tid * 16,
                           g_hn + ch2 * 256 + tid * 4);
            }
            CP_COMMIT();
        }

        if (st == 3) {
            const float* hnc = (const float*)(smem + HN_OFF + ((ch & 1) << 10));
            int n0 = ch * 256 + wn * 64 + (lane & 3) * 2;
            int l0 = wn * 64 + (lane & 3) * 2;
#pragma unroll
            for (int mt = 0; mt < 4; ++mt) {
#pragma unroll
                for (int nt = 0; nt < 8; ++nt) {
                    int c0 = n0 + nt * 8;
                    float2 h = *(const float2*)(hnc + l0 + nt * 8);
                    upd(tb[2 * mt], ts[2 * mt], tix[2 * mt], d[mt][nt][0] - h.x, c0);
                    upd(tb[2 * mt], ts[2 * mt], tix[2 * mt], d[mt][nt][1] - h.y, c0 + 1);
                    upd(tb[2 * mt + 1], ts[2 * mt + 1], tix[2 * mt + 1], d[mt][nt][2] - h.x, c0);
                    upd(tb[2 * mt + 1], ts[2 * mt + 1], tix[2 * mt + 1], d[mt][nt][3] - h.y, c0 + 1);
                }
            }
        }
    }

#pragma unroll
    for (int k = 0; k < 8; ++k) {
#pragma unroll
        for (int off = 1; off <= 2; off <<= 1) {
            float ob = __shfl_xor_sync(0xffffffffu, tb[k], off);
            float os = __shfl_xor_sync(0xffffffffu, ts[k], off);
            int   oi = __shfl_xor_sync(0xffffffffu, tix[k], off);
            if (ob > tb[k]) { ts[k] = fmaxf(tb[k], os); tb[k] = ob; tix[k] = oi; }
            else if (ob == tb[k]) { ts[k] = tb[k]; if (oi < tix[k]) tix[k] = oi; }
            else { ts[k] = fmaxf(ts[k], ob); }
        }
    }

    __syncthreads();
    float* rb = (float*)smem;
    float* rs = rb + 512;
    int*   ri = (int*)(rs + 512);
    if ((lane & 3) == 0) {
#pragma unroll
        for (int k = 0; k < 8; ++k) {
            int tl = wm * 64 + (k >> 1) * 16 + (lane >> 2) + (k & 1) * 8;
            rb[wn * 128 + tl] = tb[k];
            rs[wn * 128 + tl] = ts[k];
            ri[wn * 128 + tl] = tix[k];
        }
    }
    __syncthreads();
    if (tid < 128) {
        float b = rb[tid], s = rs[tid]; int i = ri[tid];
#pragma unroll
        for (int w = 1; w < 4; ++w) {
            float ob = rb[w * 128 + tid], os = rs[w * 128 + tid];
            int oi = ri[w * 128 + tid];
            if (ob > b) { s = fmaxf(b, os); b = ob; i = oi; }
            else if (ob == b) { s = b; if (oi < i) i = oi; }
            else { s = fmaxf(s, ob); }
        }
        int tok = t0g + tid;
        g_code[tok] = i;
        int fl = (b - s < TAU) ? 1 : 0;
        g_flag[tok] = fl;
        if (fl) {
            g_best64[tok] = 0ull;
            int p = atomicAdd(&g_qn, 1);
            g_queue[p] = tok;
        }
    }
}

// ---------------- Kernel 4: throughput rescore (exact fp32 mini-GEMM) -----
// grid (128 code-slices, 8 token-tiles grid-strided). Block: 64 codes staged
// in smem + 32 flagged x-vectors (transposed); 8 warps x (8 codes x 32 toks);
// winners merged via atomicMax on packed (score,idx).
__global__ void __launch_bounds__(256, 1)
vq_rescore(const float* __restrict__ x, const float* __restrict__ w) {
    extern __shared__ float rsm[];
    float* cs = rsm;                 // [64][260]
    float* xs = rsm + RS_CS_F;       // [256][33] (c-major, token minor)
    int tid = threadIdx.x, lane = tid & 31, wrp = tid >> 5;
    int qn = g_qn;
    if (qn == 0) return;

    int code0 = blockIdx.x << 6;
    // stage 64 codes (coalesced float4)
#pragma unroll
    for (int i = 0; i < 16; ++i) {
        int g = i * 256 + tid;
        int code = g >> 6, q = g & 63;
        ((float4*)(cs + code * 260))[q] =
            *(const float4*)(w + (size_t)(code0 + code) * 256 + q * 4);
    }
    // per-warp hn for its 8 codes
    float hn8[8];
#pragma unroll
    for (int c8 = 0; c8 < 8; ++c8) hn8[c8] = g_hn[code0 + wrp * 8 + c8];

    for (int tile = blockIdx.y; tile * 32 < qn; tile += (int)gridDim.y) {
        int tbase = tile * 32;
        int ntok = min(32, qn - tbase);
        __syncthreads();   // protect xs reuse across tiles (and after cs store)
        // stage x vectors transposed: xs[c*33 + tok]
#pragma unroll
        for (int i = 0; i < 32; ++i) {
            int g = i * 256 + tid;
            int c = g >> 5, tok = g & 31;
            if (tok < ntok) {
                int t = g_queue[tbase + tok];
                int b = t >> 10, hw = t & 1023;
                xs[c * 33 + tok] = x[((size_t)b * 256 + c) * 1024 + hw];
            }
        }
        __syncthreads();

        int myoff = (lane < ntok) ? lane : 0;
        float acc[8];
#pragma unroll
        for (int c8 = 0; c8 < 8; ++c8) acc[c8] = 0.f;
#pragma unroll
        for (int kc = 0; kc < 16; ++kc) {
            float xr[16];
#pragma unroll
            for (int j = 0; j < 16; ++j) xr[j] = xs[(kc * 16 + j) * 33 + myoff];
#pragma unroll
            for (int c8 = 0; c8 < 8; ++c8) {
                const float4* cr = (const float4*)(cs + (wrp * 8 + c8) * 260 + kc * 16);
#pragma unroll
                for (int v = 0; v < 4; ++v) {
                    float4 cv = cr[v];
                    acc[c8] = fmaf(xr[v * 4 + 0], cv.x, acc[c8]);
                    acc[c8] = fmaf(xr[v * 4 + 1], cv.y, acc[c8]);
                    acc[c8] = fmaf(xr[v * 4 + 2], cv.z, acc[c8]);
                    acc[c8] = fmaf(xr[v * 4 + 3], cv.w, acc[c8]);
                }
            }
        }
        // local argmax over 8 codes (ascending, strict >) then global merge
        float best = acc[0] - hn8[0]; int bi = code0 + wrp * 8;
#pragma unroll
        for (int c8 = 1; c8 < 8; ++c8) {
            float v = acc[c8] - hn8[c8];
            if (v > best) { best = v; bi = code0 + wrp * 8 + c8; }
        }
        if (lane < ntok) {
            int t = g_queue[tbase + lane];
            atomicMax(&g_best64[t], pack_si(best, bi));
        }
    }
}

// ---------------- Kernel 5: gather x_q + loss partials (+rescore merge) ---
__global__ void vq_gather(const float* __restrict__ x, const float* __restrict__ w,
                          float* __restrict__ out) {
    int bx = blockIdx.x;
    int b = bx >> 5, hw0 = (bx & 31) << 5;
    int tid = threadIdx.x;
    int hwl = tid & 31, cg = tid >> 5;
    int t = b * HW_ + hw0 + hwl;
    int k;
    if (g_flag[t]) {
        unsigned long long key = g_best64[t];
        k = (int)(0xFFFFFFFFu - (uint32_t)(key & 0xFFFFFFFFull));
        if (cg == 0) g_code[t] = k;   // merge for finalize
    } else {
        k = g_code[t];
    }
    const float* e  = w + (size_t)k * C_;
    const float* xb = x + (size_t)b * (C_ * HW_) + hw0 + hwl;
    float* ob = out + (size_t)b * (C_ * HW_) + hw0 + hwl;
    float ls = 0.f;
#pragma unroll
    for (int p = 0; p < 8; ++p) {
        int c0 = ((p << 3) + cg) << 2;
        float4 ev = *(const float4*)(e + c0);
#pragma unroll
        for (int j = 0; j < 4; ++j) {
            int c = c0 + j;
            float v  = f4get(ev, j);
            float xv = xb[(size_t)c * HW_];
            ob[(size_t)c * HW_] = v;
            float dd = v - xv;
            ls += dd * dd;
        }
    }
#pragma unroll
    for (int off = 16; off > 0; off >>= 1)
        ls += __shfl_down_sync(0xffffffffu, ls, off);
    __shared__ float ws[8];
    if ((tid & 31) == 0) ws[tid >> 5] = ls;
    __syncthreads();
    if (tid == 0) {
        float s = 0.f;
#pragma unroll
        for (int i = 0; i < 8; ++i) s += ws[i];
        g_partial[bx] = (double)s;
    }
}

// ---------------- Kernel 6: finalize ----------------
__global__ void vq_finalize(float* __restrict__ out) {
    int idx = blockIdx.x * 256 + threadIdx.x;
    if (idx < NTOK) out[CODE_OFF + idx] = (float)g_code[idx];
    if (idx == 0) {
        double s = 0.0;
        for (int i = 0; i < 512; ++i) s += g_partial[i];
        out[LOSS_OFF] = (float)(1.25 * s / (double)XQ_SIZE);
    }
}

// ---------------- Launch ----------------
extern "C" void kernel_launch(void* const* d_in, const int* in_sizes, int n_in,
                              void* d_out, int out_size) {
    const float* x = (const float*)d_in[0];
    const float* w = (const float*)d_in[1];
    float* out = (float*)d_out;

    cudaFuncSetAttribute((const void*)vq_argmax_mma,
                         cudaFuncAttributeMaxDynamicSharedMemorySize, SMEM_TOTAL);
    cudaFuncSetAttribute((const void*)vq_rescore,
                         cudaFuncAttributeMaxDynamicSharedMemorySize, RS_SMEM);

    vq_prep<<<dim3(8, 32, 16), dim3(32, 8)>>>(x);
    vq_wprep<<<KCODE, 256>>>(w);
    vq_argmax_mma<<<128, 256, SMEM_TOTAL>>>();
    vq_rescore<<<dim3(128, 8), 256, RS_SMEM>>>(x, w);
    vq_gather<<<512, 256>>>(x, w, out);
    vq_finalize<<<64, 256>>>(out);
}

// round 9
// speedup vs baseline: 3.9558x; 1.5406x over previous
#include <cuda_runtime.h>
#include <cuda_fp16.h>
#include <math_constants.h>
#include <cstdint>

#define B_    16
#define C_    256
#define HW_   1024
#define NTOK  16384
#define KCODE 8192
#define XQ_SIZE  4194304
#define LOSS_OFF 4194304
#define CODE_OFF 4194305
#define TAU   3e-3f

// A: 64 rows x 512B (256 fp16) + 16 pad = 528B pitch
#define A_PITCH   528
#define A_BYTES   (64 * A_PITCH)             // 33792
// B stage: 256 codes x 128B (64 fp16) + 16 pad = 144B pitch
#define B_PITCH   144
#define B_STAGE   (256 * B_PITCH)            // 36864
#define B_OFF     A_BYTES
#define HN_OFF    (A_BYTES + 2 * B_STAGE)    // 107520
#define SMEM_TOTAL (HN_OFF + 2048)           // 109568  (2 CTAs/SM)

// rescore smem: cs[64][260] + xsT[256][33]  (floats)
#define RS_CS_F   (64 * 260)
#define RS_XS_F   (256 * 33)
#define RS_SMEM   ((RS_CS_F + RS_XS_F) * 4)  // 100352

// ---------------- Device scratch ----------------
__device__ __align__(256) __half g_A[NTOK * 256];    // xh per token
__device__ __align__(256) __half g_Bw[KCODE * 256];  // eh per code
__device__ __align__(256) float g_hn[KCODE];
__device__ int    g_code[NTOK];
__device__ int    g_flag[NTOK];
__device__ int    g_qn;
__device__ int    g_queue[NTOK];
__device__ unsigned long long g_best64[NTOK];
__device__ double g_partial[512];

// ---------------- helpers ----------------
__device__ __forceinline__ uint32_t smem_u32(const void* p) {
    uint32_t a;
    asm("{ .reg .u64 t; cvta.to.shared.u64 t, %1; cvt.u32.u64 %0, t; }" : "=r"(a) : "l"(p));
    return a;
}
__device__ __forceinline__ void cp_async16(uint32_t dst, const void* src) {
    asm volatile("cp.async.cg.shared.global [%0], [%1], 16;" :: "r"(dst), "l"(src) : "memory");
}
#define CP_COMMIT() asm volatile("cp.async.commit_group;" ::: "memory")
#define CP_WAIT(n)  asm volatile("cp.async.wait_group %0;" :: "n"(n) : "memory")

__device__ __forceinline__ void ldsm4(uint32_t* r, uint32_t addr) {
    asm volatile("ldmatrix.sync.aligned.m8n8.x4.shared.b16 {%0,%1,%2,%3}, [%4];"
                 : "=r"(r[0]), "=r"(r[1]), "=r"(r[2]), "=r"(r[3]) : "r"(addr));
}
__device__ __forceinline__ void mma_fp16(float* d, const uint32_t* a, const uint32_t* b) {
    asm volatile("mma.sync.aligned.m16n8k16.row.col.f32.f16.f16.f32 "
                 "{%0,%1,%2,%3}, {%4,%5,%6,%7}, {%8,%9}, {%0,%1,%2,%3};"
                 : "+f"(d[0]), "+f"(d[1]), "+f"(d[2]), "+f"(d[3])
                 : "r"(a[0]), "r"(a[1]), "r"(a[2]), "r"(a[3]), "r"(b[0]), "r"(b[1]));
}
__device__ __forceinline__ float f4get(const float4& v, int q) {
    switch (q) { case 0: return v.x; case 1: return v.y; case 2: return v.z; default: return v.w; }
}
__device__ __forceinline__ void upd(float& b, float& s, int& i, float v, int c) {
    if (v > b) { s = b; b = v; i = c; }
    else if (v > s) s = v;
}
// order-preserving (score, idx) pack: higher score wins; ties -> smaller idx.
__device__ __forceinline__ unsigned long long pack_si(float s, int idx) {
    uint32_t u = __float_as_uint(s);
    u = (u & 0x80000000u) ? ~u : (u | 0x80000000u);
    return ((unsigned long long)u << 32) | (uint32_t)(0xFFFFFFFFu - (uint32_t)idx);
}

// ---------------- Kernel 1: x -> token-major fp16 ----------------
__global__ void vq_prep(const float* __restrict__ x) {
    __shared__ float tile[32][33];
    int c0 = blockIdx.x << 5, hw0 = blockIdx.y << 5, b = blockIdx.z;
    const float* xb = x + (size_t)b * (C_ * HW_);
#pragma unroll
    for (int k = 0; k < 4; ++k)
        tile[threadIdx.y + k * 8][threadIdx.x] =
            xb[(size_t)(c0 + threadIdx.y + k * 8) * HW_ + hw0 + threadIdx.x];
    __syncthreads();
#pragma unroll
    for (int k = 0; k < 4; ++k) {
        int token = b * HW_ + hw0 + threadIdx.y + k * 8;
        int c = c0 + threadIdx.x;
        g_A[(size_t)token * 256 + c] = __float2half_rn(tile[threadIdx.x][threadIdx.y + k * 8]);
    }
}

// ---------------- Kernel 2: w -> fp16 eh + hn + queue reset ----------
__global__ void vq_wprep(const float* __restrict__ w) {
    int k = blockIdx.x, c = threadIdx.x;
    if (k == 0 && c == 0) g_qn = 0;
    float e = w[(size_t)k * C_ + c];
    g_Bw[(size_t)k * 256 + c] = __float2half_rn(e);
    float s = e * e;
#pragma unroll
    for (int off = 16; off > 0; off >>= 1)
        s += __shfl_down_sync(0xffffffffu, s, off);
    __shared__ float ws[8];
    if ((c & 31) == 0) ws[c >> 5] = s;
    __syncthreads();
    if (c == 0) {
        float t = 0.f;
#pragma unroll
        for (int i = 0; i < 8; ++i) t += ws[i];
        g_hn[k] = 0.5f * t;
    }
}

// ---------------- Kernel 3: fp16 HMMA GEMM + fused argmax ----------------
// 256 CTAs x 64 tokens, 2 CTAs/SM. score = xh.eh (err ~3.2e-4 RMS, TAU=3e-3).
// 128 gstages = 32 chunks (256 codes) x 4 k-chunks (64 k).
__device__ __forceinline__ void issue_stage(uint32_t sb, int slot, int gs, int tid) {
    int ch = gs >> 2, kc = gs & 3;
    const __half* src = g_Bw + (size_t)ch * (256 * 256) + kc * 64;
    uint32_t dst = sb + B_OFF + slot * B_STAGE;
#pragma unroll
    for (int i = 0; i < 8; ++i) {
        int g = i * 256 + tid;
        int code = g >> 3, q = g & 7;
        cp_async16(dst + code * B_PITCH + q * 16, src + (size_t)code * 256 + q * 8);
    }
}

__global__ void __launch_bounds__(256, 2) vq_argmax_mma() {
    extern __shared__ char smem[];
    uint32_t sb = smem_u32(smem);
    int tid = threadIdx.x, lane = tid & 31, wid = tid >> 5;
    int wm = wid >> 2, wn = wid & 3;
    int t0g = blockIdx.x << 6;

    // Prologue: A tile (64x512B) + stage0 + hn(chunk0); then stage1
#pragma unroll
    for (int i = 0; i < 8; ++i) {
        int g = i * 256 + tid;
        int row = g >> 5, q = g & 31;
        cp_async16(sb + row * A_PITCH + q * 16, g_A + (size_t)(t0g + row) * 256 + q * 8);
    }
    issue_stage(sb, 0, 0, tid);
    if (tid < 64) cp_async16(sb + HN_OFF + tid * 16, g_hn + tid * 4);
    CP_COMMIT();
    issue_stage(sb, 1, 1, tid);
    CP_COMMIT();

    uint32_t a_base = sb + (wm * 32 + (lane & 15)) * A_PITCH + (lane >> 4) * 16;
    uint32_t b_base = B_OFF +
        (uint32_t)(wn * 64 + ((lane >> 4) & 1) * 8 + (lane & 7)) * B_PITCH +
        ((lane >> 3) & 1) * 16;

    float tb[4], ts[4]; int tix[4];
#pragma unroll
    for (int k = 0; k < 4; ++k) { tb[k] = -CUDART_INF_F; ts[k] = -CUDART_INF_F; tix[k] = 0x7fffffff; }

    float d[2][8][4];

    for (int gs = 0; gs < 128; ++gs) {
        int ch = gs >> 2, kc = gs & 3;
        if (kc == 0) {
#pragma unroll
            for (int mt = 0; mt < 2; ++mt)
#pragma unroll
                for (int nt = 0; nt < 8; ++nt)
#pragma unroll
                    for (int q = 0; q < 4; ++q) d[mt][nt][q] = 0.f;
        }

        CP_WAIT(1);
        __syncthreads();
        uint32_t bst = sb + (gs & 1) * B_STAGE + b_base;
        uint32_t ak = a_base + (uint32_t)(kc * 128);
#pragma unroll
        for (int j = 0; j < 4; ++j) {
            uint32_t ar[2][4];
#pragma unroll
            for (int mt = 0; mt < 2; ++mt)
                ldsm4(ar[mt], ak + mt * (16 * A_PITCH) + j * 32);
            uint32_t br[8][2];
#pragma unroll
            for (int p = 0; p < 4; ++p) {
                uint32_t r[4];
                ldsm4(r, bst + p * (16 * B_PITCH) + j * 32);
                br[2 * p][0] = r[0]; br[2 * p][1] = r[1];
                br[2 * p + 1][0] = r[2]; br[2 * p + 1][1] = r[3];
            }
#pragma unroll
            for (int mt = 0; mt < 2; ++mt)
#pragma unroll
                for (int nt = 0; nt < 8; ++nt)
                    mma_fp16(d[mt][nt], ar[mt], br[nt]);
        }
        __syncthreads();

        int g2 = gs + 2;
        if (g2 < 128) {
            issue_stage(sb, g2 & 1, g2, tid);
            if (kc == 0 && tid < 64 && ch + 1 < 32) {
                int ch2 = ch + 1;
                cp_async16(sb + HN_OFF + ((ch2 & 1) << 10) + tid * 16,
                           g_hn + ch2 * 256 + tid * 4);
            }
            CP_COMMIT();
        }

        if (kc == 3) {
            const float* hnc = (const float*)(smem + HN_OFF + ((ch & 1) << 10));
            int n0 = ch * 256 + wn * 64 + (lane & 3) * 2;
            int l0 = wn * 64 + (lane & 3) * 2;
#pragma unroll
            for (int mt = 0; mt < 2; ++mt) {
#pragma unroll
                for (int nt = 0; nt < 8; ++nt) {
                    int c0 = n0 + nt * 8;
                    float2 h = *(const float2*)(hnc + l0 + nt * 8);
                    upd(tb[2 * mt], ts[2 * mt], tix[2 * mt], d[mt][nt][0] - h.x, c0);
                    upd(tb[2 * mt], ts[2 * mt], tix[2 * mt], d[mt][nt][1] - h.y, c0 + 1);
                    upd(tb[2 * mt + 1], ts[2 * mt + 1], tix[2 * mt + 1], d[mt][nt][2] - h.x, c0);
                    upd(tb[2 * mt + 1], ts[2 * mt + 1], tix[2 * mt + 1], d[mt][nt][3] - h.y, c0 + 1);
                }
            }
        }
    }

    // merge across the 4 lanes of each quad (different code columns)
#pragma unroll
    for (int k = 0; k < 4; ++k) {
#pragma unroll
        for (int off = 1; off <= 2; off <<= 1) {
            float ob = __shfl_xor_sync(0xffffffffu, tb[k], off);
            float os = __shfl_xor_sync(0xffffffffu, ts[k], off);
            int   oi = __shfl_xor_sync(0xffffffffu, tix[k], off);
            if (ob > tb[k]) { ts[k] = fmaxf(tb[k], os); tb[k] = ob; tix[k] = oi; }
            else if (ob == tb[k]) { ts[k] = tb[k]; if (oi < tix[k]) tix[k] = oi; }
            else { ts[k] = fmaxf(ts[k], ob); }
        }
    }

    __syncthreads();   // done with A/B smem; reuse for reduction
    float* rb = (float*)smem;          // [4][64]
    float* rs = rb + 256;              // [4][64]
    int*   ri = (int*)(rs + 256);      // [4][64]
    if ((lane & 3) == 0) {
#pragma unroll
        for (int k = 0; k < 4; ++k) {
            int tl = wm * 32 + (k >> 1) * 16 + (lane >> 2) + (k & 1) * 8;
            rb[wn * 64 + tl] = tb[k];
            rs[wn * 64 + tl] = ts[k];
            ri[wn * 64 + tl] = tix[k];
        }
    }
    __syncthreads();
    if (tid < 64) {
        float b = rb[tid], s = rs[tid]; int i = ri[tid];
#pragma unroll
        for (int w = 1; w < 4; ++w) {
            float ob = rb[w * 64 + tid], os = rs[w * 64 + tid];
            int oi = ri[w * 64 + tid];
            if (ob > b) { s = fmaxf(b, os); b = ob; i = oi; }
            else if (ob == b) { s = b; if (oi < i) i = oi; }
            else { s = fmaxf(s, ob); }
        }
        int tok = t0g + tid;
        g_code[tok] = i;
        int fl = (b - s < TAU) ? 1 : 0;
        g_flag[tok] = fl;
        if (fl) {
            g_best64[tok] = 0ull;
            int p = atomicAdd(&g_qn, 1);
            g_queue[p] = tok;
        }
    }
}

// ---------------- Kernel 4: throughput rescore (exact fp32 mini-GEMM) -----
__global__ void __launch_bounds__(256, 1)
vq_rescore(const float* __restrict__ x, const float* __restrict__ w) {
    extern __shared__ float rsm[];
    float* cs = rsm;                 // [64][260]
    float* xs = rsm + RS_CS_F;       // [256][33]
    int tid = threadIdx.x, lane = tid & 31, wrp = tid >> 5;
    int qn = g_qn;
    if (qn == 0) return;
    if ((int)blockIdx.y * 32 >= qn) return;   // inactive tile rows exit early

    int code0 = blockIdx.x << 6;
#pragma unroll
    for (int i = 0; i < 16; ++i) {
        int g = i * 256 + tid;
        int code = g >> 6, q = g & 63;
        ((float4*)(cs + code * 260))[q] =
            *(const float4*)(w + (size_t)(code0 + code) * 256 + q * 4);
    }
    float hn8[8];
#pragma unroll
    for (int c8 = 0; c8 < 8; ++c8) hn8[c8] = g_hn[code0 + wrp * 8 + c8];

    for (int tile = blockIdx.y; tile * 32 < qn; tile += (int)gridDim.y) {
        int tbase = tile * 32;
        int ntok = min(32, qn - tbase);
        __syncthreads();
#pragma unroll
        for (int i = 0; i < 32; ++i) {
            int g = i * 256 + tid;
            int c = g >> 5, tok = g & 31;
            if (tok < ntok) {
                int t = g_queue[tbase + tok];
                int b = t >> 10, hw = t & 1023;
                xs[c * 33 + tok] = x[((size_t)b * 256 + c) * 1024 + hw];
            }
        }
        __syncthreads();

        int myoff = (lane < ntok) ? lane : 0;
        float acc[8];
#pragma unroll
        for (int c8 = 0; c8 < 8; ++c8) acc[c8] = 0.f;
#pragma unroll
        for (int kc = 0; kc < 16; ++kc) {
            float xr[16];
#pragma unroll
            for (int j = 0; j < 16; ++j) xr[j] = xs[(kc * 16 + j) * 33 + myoff];
#pragma unroll
            for (int c8 = 0; c8 < 8; ++c8) {
                const float4* cr = (const float4*)(cs + (wrp * 8 + c8) * 260 + kc * 16);
#pragma unroll
                for (int v = 0; v < 4; ++v) {
                    float4 cv = cr[v];
                    acc[c8] = fmaf(xr[v * 4 + 0], cv.x, acc[c8]);
                    acc[c8] = fmaf(xr[v * 4 + 1], cv.y, acc[c8]);
                    acc[c8] = fmaf(xr[v * 4 + 2], cv.z, acc[c8]);
                    acc[c8] = fmaf(xr[v * 4 + 3], cv.w, acc[c8]);
                }
            }
        }
        float best = acc[0] - hn8[0]; int bi = code0 + wrp * 8;
#pragma unroll
        for (int c8 = 1; c8 < 8; ++c8) {
            float v = acc[c8] - hn8[c8];
            if (v > best) { best = v; bi = code0 + wrp * 8 + c8; }
        }
        if (lane < ntok) {
            int t = g_queue[tbase + lane];
            atomicMax(&g_best64[t], pack_si(best, bi));
        }
    }
}

// ---------------- Kernel 5: gather x_q + loss partials (+rescore merge) ---
__global__ void vq_gather(const float* __restrict__ x, const float* __restrict__ w,
                          float* __restrict__ out) {
    int bx = blockIdx.x;
    int b = bx >> 5, hw0 = (bx & 31) << 5;
    int tid = threadIdx.x;
    int hwl = tid & 31, cg = tid >> 5;
    int t = b * HW_ + hw0 + hwl;
    int k;
    if (g_flag[t]) {
        unsigned long long key = g_best64[t];
        k = (int)(0xFFFFFFFFu - (uint32_t)(key & 0xFFFFFFFFull));
        if (cg == 0) g_code[t] = k;
    } else {
        k = g_code[t];
    }
    const float* e  = w + (size_t)k * C_;
    const float* xb = x + (size_t)b * (C_ * HW_) + hw0 + hwl;
    float* ob = out + (size_t)b * (C_ * HW_) + hw0 + hwl;
    float ls = 0.f;
#pragma unroll
    for (int p = 0; p < 8; ++p) {
        int c0 = ((p << 3) + cg) << 2;
        float4 ev = *(const float4*)(e + c0);
#pragma unroll
        for (int j = 0; j < 4; ++j) {
            int c = c0 + j;
            float v  = f4get(ev, j);
            float xv = xb[(size_t)c * HW_];
            ob[(size_t)c * HW_] = v;
            float dd = v - xv;
            ls += dd * dd;
        }
    }
#pragma unroll
    for (int off = 16; off > 0; off >>= 1)
        ls += __shfl_down_sync(0xffffffffu, ls, off);
    __shared__ float ws[8];
    if ((tid & 31) == 0) ws[tid >> 5] = ls;
    __syncthreads();
    if (tid == 0) {
        float s = 0.f;
#pragma unroll
        for (int i = 0; i < 8; ++i) s += ws[i];
        g_partial[bx] = (double)s;
    }
}

// ---------------- Kernel 6: finalize ----------------
__global__ void vq_finalize(float* __restrict__ out) {
    int idx = blockIdx.x * 256 + threadIdx.x;
    if (idx < NTOK) out[CODE_OFF + idx] = (float)g_code[idx];
    if (idx == 0) {
        double s = 0.0;
        for (int i = 0; i < 512; ++i) s += g_partial[i];
        out[LOSS_OFF] = (float)(1.25 * s / (double)XQ_SIZE);
    }
}

// ---------------- Launch ----------------
extern "C" void kernel_launch(void* const* d_in, const int* in_sizes, int n_in,
                              void* d_out, int out_size) {
    const float* x = (const float*)d_in[0];
    const float* w = (const float*)d_in[1];
    float* out = (float*)d_out;

    cudaFuncSetAttribute((const void*)vq_argmax_mma,
                         cudaFuncAttributeMaxDynamicSharedMemorySize, SMEM_TOTAL);
    cudaFuncSetAttribute((const void*)vq_rescore,
                         cudaFuncAttributeMaxDynamicSharedMemorySize, RS_SMEM);

    vq_prep<<<dim3(8, 32, 16), dim3(32, 8)>>>(x);
    vq_wprep<<<KCODE, 256>>>(w);
    vq_argmax_mma<<<256, 256, SMEM_TOTAL>>>();
    vq_rescore<<<dim3(128, 16), 256, RS_SMEM>>>(x, w);
    vq_gather<<<512, 256>>>(x, w, out);
    vq_finalize<<<64, 256>>>(out);
}